// round 2
// baseline (speedup 1.0000x reference)
#include <cuda_runtime.h>

// YOLOv1 loss on GB300. Streaming reduction: one CTA per batch item.
// Accumulators: [0]=cls, [1]=obj_conf, [2]=noobj, [3]=coord(cxcy+wh)
__device__ double g_acc[4];

#define CELLS 49
#define CH 30
#define PERB (CELLS * CH)   // 1470 floats per batch item per tensor
#define NTHREADS 128

__global__ void zero_acc_kernel() {
    if (threadIdx.x < 4) g_acc[threadIdx.x] = 0.0;
}

__global__ __launch_bounds__(NTHREADS) void yolo_loss_kernel(
    const float* __restrict__ pred, const float* __restrict__ targ) {
    __shared__ float sp[PERB];
    __shared__ float st[PERB];
    __shared__ float bpx[98][4];   // pred boxes xyxy (obj cells only, compacted)
    __shared__ float btx[98][4];   // target boxes xyxy
    __shared__ int   boxoff[98];   // smem offset (cell*30 + k*5) for each compacted box
    __shared__ int   cnt;
    __shared__ float red[4][4];    // [warp][value]

    const int b   = blockIdx.x;
    const int tid = threadIdx.x;

    // ---- Phase A: cooperative vectorized load (8-byte aligned: 1470*4 % 8 == 0)
    const float2* p2 = reinterpret_cast<const float2*>(pred + (size_t)b * PERB);
    const float2* t2 = reinterpret_cast<const float2*>(targ + (size_t)b * PERB);
    float2* sp2 = reinterpret_cast<float2*>(sp);
    float2* st2 = reinterpret_cast<float2*>(st);
    #pragma unroll 2
    for (int i = tid; i < PERB / 2; i += NTHREADS) {
        sp2[i] = p2[i];
        st2[i] = t2[i];
    }
    if (tid == 0) cnt = 0;
    __syncthreads();

    // ---- Phase B: per-cell noobj + class losses; compact obj-box list with xyxy
    float noobj = 0.0f, cls = 0.0f;
    if (tid < CELLS) {
        const float* pc = sp + tid * CH;
        const float* tc = st + tid * CH;
        const float conf = tc[4];          // exactly 0.0f or 1.0f
        if (conf == 0.0f) {
            const float d4 = pc[4] - tc[4];
            const float d9 = pc[9] - tc[9];
            noobj = d4 * d4 + d9 * d9;
        } else {
            float s = 0.0f;
            #pragma unroll
            for (int c = 10; c < 30; c++) {
                const float d = pc[c] - tc[c];
                s += d * d;
            }
            cls = s;
            const int slot = atomicAdd(&cnt, 1);
            #pragma unroll
            for (int k = 0; k < 2; k++) {
                const int j   = slot * 2 + k;
                const int off = tid * CH + k * 5;
                boxoff[j] = off;
                const float pcx = sp[off], pcy = sp[off + 1];
                const float pw  = sp[off + 2], ph = sp[off + 3];
                bpx[j][0] = pcx - pw * 0.5f;  bpx[j][1] = pcy - ph * 0.5f;
                bpx[j][2] = pcx + pw * 0.5f;  bpx[j][3] = pcy + ph * 0.5f;
                const float tcx = st[off], tcy = st[off + 1];
                const float tw  = st[off + 2], th = st[off + 3];
                btx[j][0] = tcx - tw * 0.5f;  btx[j][1] = tcy - th * 0.5f;
                btx[j][2] = tcx + tw * 0.5f;  btx[j][3] = tcy + th * 0.5f;
            }
        }
    }
    __syncthreads();

    // ---- Phase C: cmask[j] = (any obj pred box overlaps target box j).
    // iou>0 <=> intersection>0 (union always positive since w,h>=0.05),
    // so no division / max is needed.
    const int nb = cnt * 2;
    float coord = 0.0f, objc = 0.0f;
    if (tid < nb) {
        const float tx0 = btx[tid][0], ty0 = btx[tid][1];
        const float tx1 = btx[tid][2], ty1 = btx[tid][3];
        bool hit = false;
        for (int i = 0; i < nb; i++) {
            const float lx = fmaxf(bpx[i][0], tx0);
            const float ly = fmaxf(bpx[i][1], ty0);
            const float rx = fminf(bpx[i][2], tx1);
            const float ry = fminf(bpx[i][3], ty1);
            const float w  = fmaxf(rx - lx, 0.0f);
            const float h  = fmaxf(ry - ly, 0.0f);
            if (w * h > 0.0f) { hit = true; break; }
        }
        if (hit) {
            const int off = boxoff[tid];
            const float dx = sp[off]     - st[off];
            const float dy = sp[off + 1] - st[off + 1];
            const float dw = sqrtf(sp[off + 2]) - sqrtf(st[off + 2]);
            const float dh = sqrtf(sp[off + 3]) - sqrtf(st[off + 3]);
            coord = dx * dx + dy * dy + dw * dw + dh * dh;
            const float dc = sp[off + 4] - st[off + 4];
            objc = dc * dc;
        }
    }

    // ---- Phase D: block reduction of (cls, objc, noobj, coord)
    float v0 = cls, v1 = objc, v2 = noobj, v3 = coord;
    #pragma unroll
    for (int o = 16; o > 0; o >>= 1) {
        v0 += __shfl_down_sync(0xffffffffu, v0, o);
        v1 += __shfl_down_sync(0xffffffffu, v1, o);
        v2 += __shfl_down_sync(0xffffffffu, v2, o);
        v3 += __shfl_down_sync(0xffffffffu, v3, o);
    }
    const int lane = tid & 31, warp = tid >> 5;
    if (lane == 0) {
        red[warp][0] = v0; red[warp][1] = v1;
        red[warp][2] = v2; red[warp][3] = v3;
    }
    __syncthreads();
    if (tid < 4) {
        const float s = red[0][tid] + red[1][tid] + red[2][tid] + red[3][tid];
        atomicAdd(&g_acc[tid], (double)s);
    }
}

__global__ void finalize_kernel(float* __restrict__ out, float invB) {
    const double cls   = g_acc[0];
    const double objc  = g_acc[1];
    const double noobj = g_acc[2];
    const double coord = g_acc[3];
    const float bcls   = (float)(cls * (double)invB);
    const float bobj   = (float)((objc + 0.5 * noobj) * (double)invB);
    const float bcoord = (float)(coord * 5.0 * (double)invB);
    out[0] = bcls + bobj + bcoord;  // batch_loss
    out[1] = bcls;                  // batch_cls_loss
    out[2] = bobj;                  // batch_obj_loss
    out[3] = bcoord;                // batch_coord_loss
}

extern "C" void kernel_launch(void* const* d_in, const int* in_sizes, int n_in,
                              void* d_out, int out_size) {
    const float* pred = (const float*)d_in[0];
    const float* targ = (const float*)d_in[1];
    float* out = (float*)d_out;
    const int B = in_sizes[0] / PERB;   // 8192

    zero_acc_kernel<<<1, 32>>>();
    yolo_loss_kernel<<<B, NTHREADS>>>(pred, targ);
    finalize_kernel<<<1, 1>>>(out, 1.0f / (float)B);
}